// round 8
// baseline (speedup 1.0000x reference)
#include <cuda_runtime.h>
#include <cstdint>

#define BATCH 131072
#define BT    64          // producer threads (batches) per block
#define NWR   96          // writer threads
#define NTHR  (BT + NWR)  // 160
#define NL    24
#define PH    6           // links per phase -> 384 B contiguous per batch-phase
#define NPHASE (NL / PH)  // 4
#define STRIDE 19         // float4 slots per batch per buffer (18 data + 1 pad)

#define BAR_SYNC(id)   asm volatile("bar.sync %0, %1;"   :: "r"(id), "r"(NTHR) : "memory")
#define BAR_ARRIVE(id) asm volatile("bar.arrive %0, %1;" :: "r"(id), "r"(NTHR) : "memory")
// barrier ids: 1+(p&1) = data-ready (even/odd), 3+(p&1) = buffer-free (even/odd)

__global__ __launch_bounds__(NTHR)
void fk_kernel(const float* __restrict__ q,
               const float* __restrict__ axes,
               const float* __restrict__ t_fix,
               float* __restrict__ out) {
    __shared__ float  s_ax[NL][3];
    __shared__ float  s_tf[NL][3];
    __shared__ __align__(16) float4 stage[2][BT * STRIDE];   // 2 x 19456 B

    int tid = threadIdx.x;
    if (tid < NL) {
        float ax = axes[tid * 3 + 0];
        float ay = axes[tid * 3 + 1];
        float az = axes[tid * 3 + 2];
        float inv = rsqrtf(ax * ax + ay * ay + az * az);
        s_ax[tid][0] = ax * inv;
        s_ax[tid][1] = ay * inv;
        s_ax[tid][2] = az * inv;
        s_tf[tid][0] = t_fix[tid * 3 + 0];
        s_tf[tid][1] = t_fix[tid * 3 + 1];
        s_tf[tid][2] = t_fix[tid * 3 + 2];
    }
    __syncthreads();

    if (tid < BT) {
        // ================= PRODUCER: compute chain, stage to smem =========
        int b = blockIdx.x * BT + tid;
        const float2* qr = reinterpret_cast<const float2*>(q + (size_t)b * NL);

        float R00 = 1.f, R01 = 0.f, R02 = 0.f;
        float R10 = 0.f, R11 = 1.f, R12 = 0.f;
        float R20 = 0.f, R21 = 0.f, R22 = 1.f;
        float t0 = 0.f, t1 = 0.f, t2 = 0.f;

        // Prefetch phase 0's three float2 (6 q values)
        float2 qn0 = qr[0], qn1 = qr[1], qn2 = qr[2];

        #pragma unroll
        for (int p = 0; p < NPHASE; p++) {
            if (p >= 2) BAR_SYNC(3 + (p & 1));   // buffer p&1 consumed (phase p-2)

            float qv[PH] = {qn0.x, qn0.y, qn1.x, qn1.y, qn2.x, qn2.y};
            if (p < NPHASE - 1) {
                qn0 = qr[(p + 1) * 3 + 0];
                qn1 = qr[(p + 1) * 3 + 1];
                qn2 = qr[(p + 1) * 3 + 2];
            }

            float4* buf = stage[p & 1];

            #pragma unroll
            for (int ll = 0; ll < PH; ll++) {
                int l = p * PH + ll;
                float s, c;
                __sincosf(qv[ll], &s, &c);
                float C = 1.f - c;

                float ax = s_ax[l][0], ay = s_ax[l][1], az = s_ax[l][2];

                // Rodrigues: Rj = c*I + s*K + (1-c)*(a a^T)
                float j00 = fmaf(C * ax, ax, c);
                float j01 = fmaf(C * ax, ay, -s * az);
                float j02 = fmaf(C * ax, az,  s * ay);
                float j10 = fmaf(C * ay, ax,  s * az);
                float j11 = fmaf(C * ay, ay, c);
                float j12 = fmaf(C * ay, az, -s * ax);
                float j20 = fmaf(C * az, ax, -s * ay);
                float j21 = fmaf(C * az, ay,  s * ax);
                float j22 = fmaf(C * az, az, c);

                // t += R @ tf (parent R)
                float tf0 = s_tf[l][0], tf1 = s_tf[l][1], tf2 = s_tf[l][2];
                t0 = fmaf(R00, tf0, fmaf(R01, tf1, fmaf(R02, tf2, t0)));
                t1 = fmaf(R10, tf0, fmaf(R11, tf1, fmaf(R12, tf2, t1)));
                t2 = fmaf(R20, tf0, fmaf(R21, tf1, fmaf(R22, tf2, t2)));

                // R = R @ Rj
                float n00 = fmaf(R00, j00, fmaf(R01, j10, R02 * j20));
                float n01 = fmaf(R00, j01, fmaf(R01, j11, R02 * j21));
                float n02 = fmaf(R00, j02, fmaf(R01, j12, R02 * j22));
                float n10 = fmaf(R10, j00, fmaf(R11, j10, R12 * j20));
                float n11 = fmaf(R10, j01, fmaf(R11, j11, R12 * j21));
                float n12 = fmaf(R10, j02, fmaf(R11, j12, R12 * j22));
                float n20 = fmaf(R20, j00, fmaf(R21, j10, R22 * j20));
                float n21 = fmaf(R20, j01, fmaf(R21, j11, R22 * j21));
                float n22 = fmaf(R20, j02, fmaf(R21, j12, R22 * j22));
                R00 = n00; R01 = n01; R02 = n02;
                R10 = n10; R11 = n11; R12 = n12;
                R20 = n20; R21 = n21; R22 = n22;

                int sbase = tid * STRIDE + ll * 3;
                buf[sbase + 0] = make_float4(R00, R01, R02, t0);
                buf[sbase + 1] = make_float4(R10, R11, R12, t1);
                buf[sbase + 2] = make_float4(R20, R21, R22, t2);
            }
            BAR_ARRIVE(1 + (p & 1));             // data for phase p ready
        }
    } else {
        // ================= WRITER: coalesced global stores =================
        int w = tid - BT;                        // 0..95
        const int  j     = w % 24;               // float4 index within phase region
        const int  bl0   = w / 24;               // first batch serviced (0..3)
        const bool isbot = (j & 3) == 3;
        const int  slot  = (j >> 2) * 3 + (j & 3);
        const float4 BOT = make_float4(0.f, 0.f, 0.f, 1.f);

        float4* gout = reinterpret_cast<float4*>(out);
        const long gbase = (long)blockIdx.x * BT * 96;   // 96 float4 per batch

        #pragma unroll
        for (int p = 0; p < NPHASE; p++) {
            BAR_SYNC(1 + (p & 1));               // wait data for phase p
            const float4* buf = stage[p & 1];

            #pragma unroll
            for (int k = 0; k < 16; k++) {
                int bl = bl0 + k * 4;
                float4 v = isbot ? BOT : buf[bl * STRIDE + slot];
                __stcs(&gout[gbase + (long)bl * 96 + p * 24 + j], v);
            }
            // Producers only ever wait for phases <= NPHASE-3 being consumed.
            if (p < NPHASE - 2) BAR_ARRIVE(3 + (p & 1));
        }
    }
}

extern "C" void kernel_launch(void* const* d_in, const int* in_sizes, int n_in,
                              void* d_out, int out_size) {
    const float* q     = (const float*)d_in[0];
    // d_in[1] = qd, unused by the reference computation
    const float* axes  = (const float*)d_in[2];
    const float* t_fix = (const float*)d_in[3];
    float* out = (float*)d_out;

    dim3 block(NTHR);
    dim3 grid(BATCH / BT);
    fk_kernel<<<grid, block>>>(q, axes, t_fix, out);
}

// round 9
// speedup vs baseline: 1.0119x; 1.0119x over previous
#include <cuda_runtime.h>
#include <cstdint>

#define BATCH 131072
#define BT    64          // producer threads (batches) per block
#define NWR   128         // writer threads
#define NTHR  (BT + NWR)  // 192
#define NL    24
#define PH    4           // links per phase
#define NPHASE (NL / PH)  // 6
#define STRIDE 13         // float4 slots per batch per buffer (12 data + 1 pad)

#define BAR_SYNC(id)   asm volatile("bar.sync %0, %1;"   :: "r"(id), "r"(NTHR) : "memory")
#define BAR_ARRIVE(id) asm volatile("bar.arrive %0, %1;" :: "r"(id), "r"(NTHR) : "memory")
// barrier ids: 1+(p&1) = data-ready (even/odd), 3+(p&1) = buffer-free (even/odd)

__global__ __launch_bounds__(NTHR, 6)
void fk_kernel(const float* __restrict__ q,
               const float* __restrict__ axes,
               const float* __restrict__ t_fix,
               float* __restrict__ out) {
    __shared__ float  s_ax[NL][3];
    __shared__ float  s_tf[NL][3];
    __shared__ __align__(16) float4 stage[2][BT * STRIDE];   // 2 x 13312 B

    int tid = threadIdx.x;
    if (tid < NL) {
        float ax = axes[tid * 3 + 0];
        float ay = axes[tid * 3 + 1];
        float az = axes[tid * 3 + 2];
        float inv = rsqrtf(ax * ax + ay * ay + az * az);
        s_ax[tid][0] = ax * inv;
        s_ax[tid][1] = ay * inv;
        s_ax[tid][2] = az * inv;
        s_tf[tid][0] = t_fix[tid * 3 + 0];
        s_tf[tid][1] = t_fix[tid * 3 + 1];
        s_tf[tid][2] = t_fix[tid * 3 + 2];
    }
    __syncthreads();

    if (tid < BT) {
        // ================= PRODUCER: compute chain, stage to smem =========
        int b = blockIdx.x * BT + tid;
        const float4* qr = reinterpret_cast<const float4*>(q + (size_t)b * NL);

        float R00 = 1.f, R01 = 0.f, R02 = 0.f;
        float R10 = 0.f, R11 = 1.f, R12 = 0.f;
        float R20 = 0.f, R21 = 0.f, R22 = 1.f;
        float t0 = 0.f, t1 = 0.f, t2 = 0.f;

        float4 qnext = qr[0];

        #pragma unroll
        for (int p = 0; p < NPHASE; p++) {
            if (p >= 2) BAR_SYNC(3 + (p & 1));   // buffer p&1 consumed (phase p-2)

            float4 qc = qnext;
            if (p < NPHASE - 1) qnext = qr[p + 1];
            float qv[PH] = {qc.x, qc.y, qc.z, qc.w};

            float4* buf = stage[p & 1];

            #pragma unroll
            for (int ll = 0; ll < PH; ll++) {
                int l = p * PH + ll;
                float s, c;
                __sincosf(qv[ll], &s, &c);
                float C = 1.f - c;

                float ax = s_ax[l][0], ay = s_ax[l][1], az = s_ax[l][2];

                // Rodrigues: Rj = c*I + s*K + (1-c)*(a a^T)
                float j00 = fmaf(C * ax, ax, c);
                float j01 = fmaf(C * ax, ay, -s * az);
                float j02 = fmaf(C * ax, az,  s * ay);
                float j10 = fmaf(C * ay, ax,  s * az);
                float j11 = fmaf(C * ay, ay, c);
                float j12 = fmaf(C * ay, az, -s * ax);
                float j20 = fmaf(C * az, ax, -s * ay);
                float j21 = fmaf(C * az, ay,  s * ax);
                float j22 = fmaf(C * az, az, c);

                // t += R @ tf (parent R)
                float tf0 = s_tf[l][0], tf1 = s_tf[l][1], tf2 = s_tf[l][2];
                t0 = fmaf(R00, tf0, fmaf(R01, tf1, fmaf(R02, tf2, t0)));
                t1 = fmaf(R10, tf0, fmaf(R11, tf1, fmaf(R12, tf2, t1)));
                t2 = fmaf(R20, tf0, fmaf(R21, tf1, fmaf(R22, tf2, t2)));

                // R = R @ Rj
                float n00 = fmaf(R00, j00, fmaf(R01, j10, R02 * j20));
                float n01 = fmaf(R00, j01, fmaf(R01, j11, R02 * j21));
                float n02 = fmaf(R00, j02, fmaf(R01, j12, R02 * j22));
                float n10 = fmaf(R10, j00, fmaf(R11, j10, R12 * j20));
                float n11 = fmaf(R10, j01, fmaf(R11, j11, R12 * j21));
                float n12 = fmaf(R10, j02, fmaf(R11, j12, R12 * j22));
                float n20 = fmaf(R20, j00, fmaf(R21, j10, R22 * j20));
                float n21 = fmaf(R20, j01, fmaf(R21, j11, R22 * j21));
                float n22 = fmaf(R20, j02, fmaf(R21, j12, R22 * j22));
                R00 = n00; R01 = n01; R02 = n02;
                R10 = n10; R11 = n11; R12 = n12;
                R20 = n20; R21 = n21; R22 = n22;

                int sbase = tid * STRIDE + ll * 3;
                buf[sbase + 0] = make_float4(R00, R01, R02, t0);
                buf[sbase + 1] = make_float4(R10, R11, R12, t1);
                buf[sbase + 2] = make_float4(R20, R21, R22, t2);
            }
            BAR_ARRIVE(1 + (p & 1));             // data for phase p ready
        }
    } else {
        // ================= WRITER: coalesced global stores =================
        int w = tid - BT;                        // 0..127
        const int  j     = w & 15;               // float4 index within phase region
        const int  bl0   = w >> 4;               // first batch serviced (0..7)
        const bool isbot = (j & 3) == 3;
        const int  slot  = (j >> 2) * 3 + (j & 3);
        const float4 BOT = make_float4(0.f, 0.f, 0.f, 1.f);

        float4* gout = reinterpret_cast<float4*>(out);
        const long gbase = (long)blockIdx.x * BT * 96;   // 96 float4 per batch

        #pragma unroll
        for (int p = 0; p < NPHASE; p++) {
            BAR_SYNC(1 + (p & 1));               // wait data for phase p
            const float4* buf = stage[p & 1];

            #pragma unroll
            for (int k = 0; k < 8; k++) {
                int bl = bl0 + k * 8;
                float4 v = isbot ? BOT : buf[bl * STRIDE + slot];
                __stcs(&gout[gbase + (long)bl * 96 + p * 16 + j], v);
            }
            // Producers only ever wait for phases <= NPHASE-3 being consumed.
            if (p < NPHASE - 2) BAR_ARRIVE(3 + (p & 1));
        }
    }
}

extern "C" void kernel_launch(void* const* d_in, const int* in_sizes, int n_in,
                              void* d_out, int out_size) {
    const float* q     = (const float*)d_in[0];
    // d_in[1] = qd, unused by the reference computation
    const float* axes  = (const float*)d_in[2];
    const float* t_fix = (const float*)d_in[3];
    float* out = (float*)d_out;

    dim3 block(NTHR);
    dim3 grid(BATCH / BT);
    fk_kernel<<<grid, block>>>(q, axes, t_fix, out);
}

// round 10
// speedup vs baseline: 1.0138x; 1.0018x over previous
#include <cuda_runtime.h>
#include <cstdint>

#define BATCH 131072
#define BT    64          // producer threads (batches) per block
#define NWR   128         // writer threads
#define NTHR  (BT + NWR)  // 192
#define NL    24
#define PH    4           // links per phase
#define NPHASE (NL / PH)  // 6
#define NBUF  3           // ring depth
#define STRIDE 13         // float4 slots per batch per buffer (12 data + 1 pad)

#define BAR_SYNC(id)   asm volatile("bar.sync %0, %1;"   :: "r"(id), "r"(NTHR) : "memory")
#define BAR_ARRIVE(id) asm volatile("bar.arrive %0, %1;" :: "r"(id), "r"(NTHR) : "memory")
// barrier ids: 1+buf = data-ready(buf), 4+buf = buffer-free(buf), buf = p % 3

__global__ __launch_bounds__(NTHR, 5)
void fk_kernel(const float* __restrict__ q,
               const float* __restrict__ axes,
               const float* __restrict__ t_fix,
               float* __restrict__ out) {
    __shared__ float  s_ax[NL][3];
    __shared__ float  s_tf[NL][3];
    __shared__ __align__(16) float4 stage[NBUF][BT * STRIDE];   // 3 x 13312 B

    int tid = threadIdx.x;
    if (tid < NL) {
        float ax = axes[tid * 3 + 0];
        float ay = axes[tid * 3 + 1];
        float az = axes[tid * 3 + 2];
        float inv = rsqrtf(ax * ax + ay * ay + az * az);
        s_ax[tid][0] = ax * inv;
        s_ax[tid][1] = ay * inv;
        s_ax[tid][2] = az * inv;
        s_tf[tid][0] = t_fix[tid * 3 + 0];
        s_tf[tid][1] = t_fix[tid * 3 + 1];
        s_tf[tid][2] = t_fix[tid * 3 + 2];
    }
    __syncthreads();

    if (tid < BT) {
        // ================= PRODUCER: compute chain, stage to smem =========
        int b = blockIdx.x * BT + tid;
        const float4* qr = reinterpret_cast<const float4*>(q + (size_t)b * NL);

        float R00 = 1.f, R01 = 0.f, R02 = 0.f;
        float R10 = 0.f, R11 = 1.f, R12 = 0.f;
        float R20 = 0.f, R21 = 0.f, R22 = 1.f;
        float t0 = 0.f, t1 = 0.f, t2 = 0.f;

        float4 qnext = qr[0];

        #pragma unroll
        for (int p = 0; p < NPHASE; p++) {
            int bufi = p % NBUF;
            if (p >= NBUF) BAR_SYNC(4 + bufi);   // buffer consumed (phase p-3)

            float4 qc = qnext;
            if (p < NPHASE - 1) qnext = qr[p + 1];
            float qv[PH] = {qc.x, qc.y, qc.z, qc.w};

            float4* buf = stage[bufi];

            #pragma unroll
            for (int ll = 0; ll < PH; ll++) {
                int l = p * PH + ll;
                float s, c;
                __sincosf(qv[ll], &s, &c);
                float C = 1.f - c;

                float ax = s_ax[l][0], ay = s_ax[l][1], az = s_ax[l][2];

                // Rodrigues: Rj = c*I + s*K + (1-c)*(a a^T)
                float j00 = fmaf(C * ax, ax, c);
                float j01 = fmaf(C * ax, ay, -s * az);
                float j02 = fmaf(C * ax, az,  s * ay);
                float j10 = fmaf(C * ay, ax,  s * az);
                float j11 = fmaf(C * ay, ay, c);
                float j12 = fmaf(C * ay, az, -s * ax);
                float j20 = fmaf(C * az, ax, -s * ay);
                float j21 = fmaf(C * az, ay,  s * ax);
                float j22 = fmaf(C * az, az, c);

                // t += R @ tf (parent R)
                float tf0 = s_tf[l][0], tf1 = s_tf[l][1], tf2 = s_tf[l][2];
                t0 = fmaf(R00, tf0, fmaf(R01, tf1, fmaf(R02, tf2, t0)));
                t1 = fmaf(R10, tf0, fmaf(R11, tf1, fmaf(R12, tf2, t1)));
                t2 = fmaf(R20, tf0, fmaf(R21, tf1, fmaf(R22, tf2, t2)));

                // R = R @ Rj
                float n00 = fmaf(R00, j00, fmaf(R01, j10, R02 * j20));
                float n01 = fmaf(R00, j01, fmaf(R01, j11, R02 * j21));
                float n02 = fmaf(R00, j02, fmaf(R01, j12, R02 * j22));
                float n10 = fmaf(R10, j00, fmaf(R11, j10, R12 * j20));
                float n11 = fmaf(R10, j01, fmaf(R11, j11, R12 * j21));
                float n12 = fmaf(R10, j02, fmaf(R11, j12, R12 * j22));
                float n20 = fmaf(R20, j00, fmaf(R21, j10, R22 * j20));
                float n21 = fmaf(R20, j01, fmaf(R21, j11, R22 * j21));
                float n22 = fmaf(R20, j02, fmaf(R21, j12, R22 * j22));
                R00 = n00; R01 = n01; R02 = n02;
                R10 = n10; R11 = n11; R12 = n12;
                R20 = n20; R21 = n21; R22 = n22;

                int sbase = tid * STRIDE + ll * 3;
                buf[sbase + 0] = make_float4(R00, R01, R02, t0);
                buf[sbase + 1] = make_float4(R10, R11, R12, t1);
                buf[sbase + 2] = make_float4(R20, R21, R22, t2);
            }
            BAR_ARRIVE(1 + bufi);                // data for phase p ready
        }
    } else {
        // ================= WRITER: coalesced global stores =================
        int w = tid - BT;                        // 0..127
        const int  j     = w & 15;               // float4 index within phase region
        const int  bl0   = w >> 4;               // first batch serviced (0..7)
        const bool isbot = (j & 3) == 3;
        const int  slot  = (j >> 2) * 3 + (j & 3);
        const float4 BOT = make_float4(0.f, 0.f, 0.f, 1.f);

        float4* gout = reinterpret_cast<float4*>(out);
        const long gbase = (long)blockIdx.x * BT * 96;   // 96 float4 per batch

        #pragma unroll
        for (int p = 0; p < NPHASE; p++) {
            int bufi = p % NBUF;
            BAR_SYNC(1 + bufi);                  // wait data for phase p
            const float4* buf = stage[bufi];

            // Gather first (8 independent LDS), then store (8 STG).
            float4 v[8];
            #pragma unroll
            for (int k = 0; k < 8; k++) {
                int bl = bl0 + k * 8;
                v[k] = isbot ? BOT : buf[bl * STRIDE + slot];
            }
            #pragma unroll
            for (int k = 0; k < 8; k++) {
                int bl = bl0 + k * 8;
                __stcs(&gout[gbase + (long)bl * 96 + p * 16 + j], v[k]);
            }
            // Producers only wait for buffers of phases p' = p+3 <= NPHASE-1.
            if (p < NPHASE - NBUF) BAR_ARRIVE(4 + bufi);
        }
    }
}

extern "C" void kernel_launch(void* const* d_in, const int* in_sizes, int n_in,
                              void* d_out, int out_size) {
    const float* q     = (const float*)d_in[0];
    // d_in[1] = qd, unused by the reference computation
    const float* axes  = (const float*)d_in[2];
    const float* t_fix = (const float*)d_in[3];
    float* out = (float*)d_out;

    dim3 block(NTHR);
    dim3 grid(BATCH / BT);
    fk_kernel<<<grid, block>>>(q, axes, t_fix, out);
}